// round 10
// baseline (speedup 1.0000x reference)
#include <cuda_runtime.h>
#include <cuda_bf16.h>

// ---------------- problem constants ----------------
#define TOPK        1000
#define NCLASSES    80
#define MAXN        500000
#define CAND_CAP    4096
#define IOU_THR     0.5f
#define SCORE_THR   0.05f

// ---------------- device scratch (static: no allocation allowed) ----------------
__device__ float        g_maxv[MAXN];
__device__ int          g_cls[MAXN];
__device__ unsigned     g_hist[2048];
__device__ unsigned     g_sel[8];          // [0]=b1 [1]=above1 [2]=b2 [3]=above2 [4]=cutoff
__device__ unsigned     g_ncand;
__device__ unsigned long long g_cand[CAND_CAP];
__device__ float4       g_topbox[1024];
__device__ int          g_topcls[1024];
__device__ unsigned     g_M[TOPK * 32];    // suppression set-mask rows (128 KB)

// ---------------- kernel 0: zero counters ----------------
__global__ void z_kernel() {
    int t = threadIdx.x;
    for (int i = t; i < 2048; i += 256) g_hist[i] = 0;
    if (t == 0) g_ncand = 0;
}

// ---------------- kernel 1: per-box thresholded max + argmax, level-1 histogram ----------------
__global__ void reduce_kernel(const float* __restrict__ scores, int N) {
    __shared__ unsigned sh[2048];
    int t = threadIdx.x;
    for (int i = t; i < 2048; i += 256) sh[i] = 0;
    __syncthreads();

    int box = blockIdx.x * blockDim.x + t;
    if (box < N) {
        const float4* row = reinterpret_cast<const float4*>(scores + (long long)box * NCLASSES);
        float best = -1.0f;
        int bestc = 0;
        #pragma unroll
        for (int q = 0; q < NCLASSES / 4; ++q) {
            float4 v = __ldg(row + q);
            float a = (v.x < SCORE_THR) ? 0.0f : v.x;
            float b = (v.y < SCORE_THR) ? 0.0f : v.y;
            float c = (v.z < SCORE_THR) ? 0.0f : v.z;
            float d = (v.w < SCORE_THR) ? 0.0f : v.w;
            int cbase = q * 4;
            if (a > best) { best = a; bestc = cbase + 0; }
            if (b > best) { best = b; bestc = cbase + 1; }
            if (c > best) { best = c; bestc = cbase + 2; }
            if (d > best) { best = d; bestc = cbase + 3; }
        }
        g_maxv[box] = best;
        g_cls[box]  = bestc;
        unsigned key = __float_as_uint(best);   // best >= 0 -> order preserving
        atomicAdd(&sh[key >> 21], 1u);
    }
    __syncthreads();
    for (int i = t; i < 2048; i += 256) {
        unsigned c = sh[i];
        if (c) atomicAdd(&g_hist[i], c);
    }
}

// ---------------- scan: find radix cutoff at each level, then zero hist ----------------
__global__ void scan_kernel(int phase) {
    __shared__ unsigned s_part[64];
    int t = threadIdx.x;
    int nbins = (phase == 3) ? 1024 : 2048;
    int chunks = nbins / 32;

    if (t < chunks) {
        unsigned s = 0;
        #pragma unroll
        for (int u = 0; u < 32; ++u) s += g_hist[t * 32 + u];
        s_part[t] = s;
    }
    __syncthreads();

    if (t == 0) {
        unsigned above_in = (phase == 1) ? 0u : ((phase == 2) ? g_sel[1] : g_sel[3]);
        unsigned cum = above_in;
        int b = 0;
        unsigned above_b = above_in;
        bool found = false;
        for (int ch = chunks - 1; ch >= 0 && !found; --ch) {
            if (cum + s_part[ch] >= (unsigned)TOPK) {
                for (int bin = ch * 32 + 31; bin >= ch * 32; --bin) {
                    unsigned c = g_hist[bin];
                    if (cum + c >= (unsigned)TOPK) { b = bin; above_b = cum; found = true; break; }
                    cum += c;
                }
            } else {
                cum += s_part[ch];
            }
        }
        if (phase == 1)      { g_sel[0] = (unsigned)b; g_sel[1] = above_b; }
        else if (phase == 2) { g_sel[2] = (unsigned)b; g_sel[3] = above_b; }
        else {
            g_sel[4] = (g_sel[0] << 21) | (g_sel[2] << 10) | (unsigned)b;
            g_ncand = 0;
        }
    }
    __syncthreads();
    for (int i = t; i < 2048; i += 256) g_hist[i] = 0;
}

// ---------------- refinement histograms ----------------
__global__ void hist2_kernel(int N) {
    __shared__ unsigned sh[2048];
    __shared__ unsigned s_b1;
    int t = threadIdx.x;
    for (int i = t; i < 2048; i += 256) sh[i] = 0;
    if (t == 0) s_b1 = g_sel[0];
    __syncthreads();
    unsigned b1 = s_b1;
    for (int i = blockIdx.x * blockDim.x + t; i < N; i += gridDim.x * blockDim.x) {
        unsigned key = __float_as_uint(g_maxv[i]);
        if ((key >> 21) == b1) atomicAdd(&sh[(key >> 10) & 2047u], 1u);
    }
    __syncthreads();
    for (int i = t; i < 2048; i += 256) {
        unsigned c = sh[i];
        if (c) atomicAdd(&g_hist[i], c);
    }
}

__global__ void hist3_kernel(int N) {
    __shared__ unsigned sh[1024];
    __shared__ unsigned s_top22;
    int t = threadIdx.x;
    for (int i = t; i < 1024; i += 256) sh[i] = 0;
    if (t == 0) s_top22 = (g_sel[0] << 11) | g_sel[2];
    __syncthreads();
    unsigned top22 = s_top22;
    for (int i = blockIdx.x * blockDim.x + t; i < N; i += gridDim.x * blockDim.x) {
        unsigned key = __float_as_uint(g_maxv[i]);
        if ((key >> 10) == top22) atomicAdd(&sh[key & 1023u], 1u);
    }
    __syncthreads();
    for (int i = t; i < 1024; i += 256) {
        unsigned c = sh[i];
        if (c) atomicAdd(&g_hist[i], c);
    }
}

// ---------------- compact candidates >= cutoff ----------------
__global__ void compact_kernel(int N) {
    __shared__ unsigned s_cut;
    int t = threadIdx.x;
    if (t == 0) s_cut = g_sel[4];
    __syncthreads();
    unsigned cut = s_cut;
    for (int i = blockIdx.x * blockDim.x + t; i < N; i += gridDim.x * blockDim.x) {
        unsigned key = __float_as_uint(g_maxv[i]);
        if (key >= cut) {
            unsigned pos = atomicAdd(&g_ncand, 1u);
            if (pos < CAND_CAP)
                g_cand[pos] = (((unsigned long long)key) << 32) | (unsigned long long)(0xFFFFFFFFu - (unsigned)i);
        }
    }
}

// ---------------- single-block bitonic sort (descending) + emit top-k ----------------
__global__ void sort_kernel(const float* __restrict__ boxes, float* __restrict__ out) {
    __shared__ unsigned long long s_key[CAND_CAP];
    int t = threadIdx.x;
    unsigned n = g_ncand;
    if (n > CAND_CAP) n = CAND_CAP;
    for (int i = t; i < CAND_CAP; i += 1024)
        s_key[i] = (i < (int)n) ? g_cand[i] : 0ULL;
    __syncthreads();

    for (int k = 2; k <= CAND_CAP; k <<= 1) {
        for (int j = k >> 1; j > 0; j >>= 1) {
            for (int i = t; i < CAND_CAP; i += 1024) {
                int ixj = i ^ j;
                if (ixj > i) {
                    unsigned long long a = s_key[i], b = s_key[ixj];
                    bool first_block = ((i & k) == 0);
                    // descending overall
                    if (first_block ? (a < b) : (a > b)) {
                        s_key[i] = b; s_key[ixj] = a;
                    }
                }
            }
            __syncthreads();
        }
    }

    if (t < TOPK) {
        unsigned long long kv = s_key[t];
        unsigned key = (unsigned)(kv >> 32);
        unsigned idx = 0xFFFFFFFFu - (unsigned)(kv & 0xFFFFFFFFu);
        out[t]            = (float)idx;
        out[TOPK + t]     = __uint_as_float(key);
        int c = g_cls[idx];
        out[2 * TOPK + t] = (float)c;
        g_topcls[t] = c;
        g_topbox[t] = __ldg(reinterpret_cast<const float4*>(boxes) + idx);
    }
    if (t >= TOPK && t < 1024) { g_topcls[t] = -1; }
}

// ---------------- multi-SM suppression-mask build (1 warp per row) ----------------
__global__ void mask_kernel() {
    int warp = blockIdx.x * (blockDim.x >> 5) + (threadIdx.x >> 5);
    if (warp >= TOPK) return;
    int lane = threadIdx.x & 31;
    int i = warp;
    float4 bi = g_topbox[i];
    float ai = (bi.z - bi.x) * (bi.w - bi.y);
    int ci = g_topcls[i];
    #pragma unroll 4
    for (int k = 0; k < 32; ++k) {
        int j = k * 32 + lane;
        bool valid = (j < TOPK);
        int jj = valid ? j : 0;
        float4 bj = g_topbox[jj];
        int cj = g_topcls[jj];
        float aj = (bj.z - bj.x) * (bj.w - bj.y);
        float ltx = fmaxf(bi.x, bj.x);
        float lty = fmaxf(bi.y, bj.y);
        float rbx = fminf(bi.z, bj.z);
        float rby = fminf(bi.w, bj.w);
        float w = fmaxf(rbx - ltx, 0.0f);
        float h = fmaxf(rby - lty, 0.0f);
        float inter = w * h;
        float den = ((ai + aj) - inter) + 1e-6f;
        // iou <= 0.5  <=>  inter <= 0.5*den   (den > 0 always)
        bool bit = valid && (cj == ci) && (inter <= 0.5f * den);
        unsigned word = __ballot_sync(0xFFFFFFFFu, bit);
        if (lane == 0) g_M[i * 32 + k] = word;
    }
}

// ---------------- single-block sequential suppression ----------------
// smem: M rows (32000 u32) + class masks (80*32 u32) + cls (1000 int)
#define SUPPRESS_SMEM ((32000 + 80 * 32 + 1000) * 4)

__global__ void suppress_kernel(float* __restrict__ out) {
    extern __shared__ unsigned smem[];
    unsigned* sM       = smem;                 // 32000
    unsigned* sClsMask = sM + 32000;           // 2560
    int*      sCls     = (int*)(sClsMask + 2560); // 1000

    int t = threadIdx.x;
    for (int i = t; i < 32000; i += 1024) sM[i] = g_M[i];
    for (int i = t; i < 2560;  i += 1024) sClsMask[i] = 0;
    if (t < TOPK) sCls[t] = g_topcls[t];
    __syncthreads();
    if (t < TOPK) atomicOr(&sClsMask[sCls[t] * 32 + (t >> 5)], 1u << (t & 31));
    __syncthreads();

    if (t < 32) {
        int lane = t;
        unsigned keep_w = (lane < 31) ? 0xFFFFFFFFu : 0x000000FFu;

        // depth-2 software prefetch of (set-row, class-row)
        unsigned set0 = sM[0 * 32 + lane];
        unsigned cls0 = sClsMask[sCls[0] * 32 + lane];
        unsigned set1 = sM[1 * 32 + lane];
        unsigned cls1 = sClsMask[sCls[1] * 32 + lane];

        for (int i = 0; i < TOPK; ++i) {
            unsigned setrow = set0, clsrow = cls0;
            set0 = set1; cls0 = cls1;
            int nx = i + 2;
            if (nx < TOPK) {
                set1 = sM[nx * 32 + lane];
                cls1 = sClsMask[sCls[nx] * 32 + lane];
            }
            unsigned kw = __shfl_sync(0xFFFFFFFFu, keep_w, i >> 5);
            unsigned apply = 0u - ((kw >> (i & 31)) & 1u);
            keep_w = (keep_w & ~(clsrow & apply)) | (setrow & apply);
        }

        #pragma unroll
        for (int b = 0; b < 32; ++b) {
            int j = lane * 32 + b;
            if (j < TOPK) out[3 * TOPK + j] = ((keep_w >> b) & 1u) ? 1.0f : 0.0f;
        }
    }
}

// ---------------- launch ----------------
extern "C" void kernel_launch(void* const* d_in, const int* in_sizes, int n_in,
                              void* d_out, int out_size) {
    const float* boxes  = (const float*)d_in[0];
    const float* scores = (const float*)d_in[1];
    float* out = (float*)d_out;
    int N = in_sizes[0] / 4;
    if (N > MAXN) N = MAXN;

    static bool attr_set = false;
    if (!attr_set) {
        cudaFuncSetAttribute(suppress_kernel,
                             cudaFuncAttributeMaxDynamicSharedMemorySize, SUPPRESS_SMEM);
        attr_set = true;
    }

    z_kernel<<<1, 256>>>();
    reduce_kernel<<<(N + 255) / 256, 256>>>(scores, N);
    scan_kernel<<<1, 256>>>(1);
    hist2_kernel<<<512, 256>>>(N);
    scan_kernel<<<1, 256>>>(2);
    hist3_kernel<<<512, 256>>>(N);
    scan_kernel<<<1, 256>>>(3);
    compact_kernel<<<512, 256>>>(N);
    sort_kernel<<<1, 1024>>>(boxes, out);
    mask_kernel<<<125, 256>>>();
    suppress_kernel<<<1, 1024, SUPPRESS_SMEM>>>(out);
}

// round 11
// speedup vs baseline: 1.0107x; 1.0107x over previous
#include <cuda_runtime.h>
#include <cuda_bf16.h>

// ---------------- problem constants ----------------
#define TOPK        1000
#define NCLASSES    80
#define MAXN        500000
#define CAND_CAP    4096
#define IOU_THR     0.5f
#define SCORE_THR   0.05f

// ---------------- device scratch (static: no allocation allowed) ----------------
__device__ float        g_maxv[MAXN];
__device__ int          g_cls[MAXN];
__device__ unsigned     g_hist[2048];
__device__ unsigned     g_sel[8];          // [0]=b1 [1]=above1 [2]=b2 [3]=above2 [4]=cutoff
__device__ unsigned     g_ncand;
__device__ unsigned long long g_cand[CAND_CAP];
__device__ float4       g_topbox[1024];
__device__ int          g_topcls[1024];
__device__ unsigned     g_M[TOPK * 32];    // suppression set-mask rows (128 KB)

// ---------------- kernel 0: zero counters ----------------
__global__ void z_kernel() {
    int t = threadIdx.x;
    for (int i = t; i < 2048; i += 256) g_hist[i] = 0;
    if (t == 0) g_ncand = 0;
}

// ---------------- kernel 1: per-box thresholded max + argmax, level-1 histogram ----------------
__global__ void reduce_kernel(const float* __restrict__ scores, int N) {
    __shared__ unsigned sh[2048];
    int t = threadIdx.x;
    for (int i = t; i < 2048; i += 256) sh[i] = 0;
    __syncthreads();

    int box = blockIdx.x * blockDim.x + t;
    if (box < N) {
        const float4* row = reinterpret_cast<const float4*>(scores + (long long)box * NCLASSES);
        float best = -1.0f;
        int bestc = 0;
        #pragma unroll
        for (int q = 0; q < NCLASSES / 4; ++q) {
            float4 v = __ldg(row + q);
            float a = (v.x < SCORE_THR) ? 0.0f : v.x;
            float b = (v.y < SCORE_THR) ? 0.0f : v.y;
            float c = (v.z < SCORE_THR) ? 0.0f : v.z;
            float d = (v.w < SCORE_THR) ? 0.0f : v.w;
            int cbase = q * 4;
            if (a > best) { best = a; bestc = cbase + 0; }
            if (b > best) { best = b; bestc = cbase + 1; }
            if (c > best) { best = c; bestc = cbase + 2; }
            if (d > best) { best = d; bestc = cbase + 3; }
        }
        g_maxv[box] = best;
        g_cls[box]  = bestc;
        unsigned key = __float_as_uint(best);   // best >= 0 -> order preserving
        atomicAdd(&sh[key >> 21], 1u);
    }
    __syncthreads();
    for (int i = t; i < 2048; i += 256) {
        unsigned c = sh[i];
        if (c) atomicAdd(&g_hist[i], c);
    }
}

// ---------------- scan: find radix cutoff at each level, then zero hist ----------------
__global__ void scan_kernel(int phase) {
    __shared__ unsigned s_part[64];
    int t = threadIdx.x;
    int nbins = (phase == 3) ? 1024 : 2048;
    int chunks = nbins / 32;

    if (t < chunks) {
        unsigned s = 0;
        #pragma unroll
        for (int u = 0; u < 32; ++u) s += g_hist[t * 32 + u];
        s_part[t] = s;
    }
    __syncthreads();

    if (t == 0) {
        unsigned above_in = (phase == 1) ? 0u : ((phase == 2) ? g_sel[1] : g_sel[3]);
        unsigned cum = above_in;
        int b = 0;
        unsigned above_b = above_in;
        bool found = false;
        for (int ch = chunks - 1; ch >= 0 && !found; --ch) {
            if (cum + s_part[ch] >= (unsigned)TOPK) {
                for (int bin = ch * 32 + 31; bin >= ch * 32; --bin) {
                    unsigned c = g_hist[bin];
                    if (cum + c >= (unsigned)TOPK) { b = bin; above_b = cum; found = true; break; }
                    cum += c;
                }
            } else {
                cum += s_part[ch];
            }
        }
        if (phase == 1)      { g_sel[0] = (unsigned)b; g_sel[1] = above_b; }
        else if (phase == 2) { g_sel[2] = (unsigned)b; g_sel[3] = above_b; }
        else {
            g_sel[4] = (g_sel[0] << 21) | (g_sel[2] << 10) | (unsigned)b;
            g_ncand = 0;
        }
    }
    __syncthreads();
    for (int i = t; i < 2048; i += 256) g_hist[i] = 0;
}

// ---------------- refinement histograms ----------------
__global__ void hist2_kernel(int N) {
    __shared__ unsigned sh[2048];
    __shared__ unsigned s_b1;
    int t = threadIdx.x;
    for (int i = t; i < 2048; i += 256) sh[i] = 0;
    if (t == 0) s_b1 = g_sel[0];
    __syncthreads();
    unsigned b1 = s_b1;
    for (int i = blockIdx.x * blockDim.x + t; i < N; i += gridDim.x * blockDim.x) {
        unsigned key = __float_as_uint(g_maxv[i]);
        if ((key >> 21) == b1) atomicAdd(&sh[(key >> 10) & 2047u], 1u);
    }
    __syncthreads();
    for (int i = t; i < 2048; i += 256) {
        unsigned c = sh[i];
        if (c) atomicAdd(&g_hist[i], c);
    }
}

__global__ void hist3_kernel(int N) {
    __shared__ unsigned sh[1024];
    __shared__ unsigned s_top22;
    int t = threadIdx.x;
    for (int i = t; i < 1024; i += 256) sh[i] = 0;
    if (t == 0) s_top22 = (g_sel[0] << 11) | g_sel[2];
    __syncthreads();
    unsigned top22 = s_top22;
    for (int i = blockIdx.x * blockDim.x + t; i < N; i += gridDim.x * blockDim.x) {
        unsigned key = __float_as_uint(g_maxv[i]);
        if ((key >> 10) == top22) atomicAdd(&sh[key & 1023u], 1u);
    }
    __syncthreads();
    for (int i = t; i < 1024; i += 256) {
        unsigned c = sh[i];
        if (c) atomicAdd(&g_hist[i], c);
    }
}

// ---------------- compact candidates >= cutoff ----------------
__global__ void compact_kernel(int N) {
    __shared__ unsigned s_cut;
    int t = threadIdx.x;
    if (t == 0) s_cut = g_sel[4];
    __syncthreads();
    unsigned cut = s_cut;
    for (int i = blockIdx.x * blockDim.x + t; i < N; i += gridDim.x * blockDim.x) {
        unsigned key = __float_as_uint(g_maxv[i]);
        if (key >= cut) {
            unsigned pos = atomicAdd(&g_ncand, 1u);
            if (pos < CAND_CAP)
                g_cand[pos] = (((unsigned long long)key) << 32) | (unsigned long long)(0xFFFFFFFFu - (unsigned)i);
        }
    }
}

// ---------------- single-block bitonic sort (descending) + emit top-k ----------------
__global__ void sort_kernel(const float* __restrict__ boxes, float* __restrict__ out) {
    __shared__ unsigned long long s_key[CAND_CAP];
    int t = threadIdx.x;
    unsigned n = g_ncand;
    if (n > CAND_CAP) n = CAND_CAP;
    for (int i = t; i < CAND_CAP; i += 1024)
        s_key[i] = (i < (int)n) ? g_cand[i] : 0ULL;
    __syncthreads();

    for (int k = 2; k <= CAND_CAP; k <<= 1) {
        for (int j = k >> 1; j > 0; j >>= 1) {
            for (int i = t; i < CAND_CAP; i += 1024) {
                int ixj = i ^ j;
                if (ixj > i) {
                    unsigned long long a = s_key[i], b = s_key[ixj];
                    bool first_block = ((i & k) == 0);
                    // descending overall
                    if (first_block ? (a < b) : (a > b)) {
                        s_key[i] = b; s_key[ixj] = a;
                    }
                }
            }
            __syncthreads();
        }
    }

    if (t < TOPK) {
        unsigned long long kv = s_key[t];
        unsigned key = (unsigned)(kv >> 32);
        unsigned idx = 0xFFFFFFFFu - (unsigned)(kv & 0xFFFFFFFFu);
        out[t]            = (float)idx;
        out[TOPK + t]     = __uint_as_float(key);
        int c = g_cls[idx];
        out[2 * TOPK + t] = (float)c;
        g_topcls[t] = c;
        g_topbox[t] = __ldg(reinterpret_cast<const float4*>(boxes) + idx);
    }
    if (t >= TOPK && t < 1024) { g_topcls[t] = -1; }
}

// ---------------- multi-SM suppression-mask build (1 warp per row) ----------------
__global__ void mask_kernel() {
    int warp = blockIdx.x * (blockDim.x >> 5) + (threadIdx.x >> 5);
    if (warp >= TOPK) return;
    int lane = threadIdx.x & 31;
    int i = warp;
    float4 bi = g_topbox[i];
    float ai = (bi.z - bi.x) * (bi.w - bi.y);
    int ci = g_topcls[i];
    #pragma unroll 4
    for (int k = 0; k < 32; ++k) {
        int j = k * 32 + lane;
        bool valid = (j < TOPK);
        int jj = valid ? j : 0;
        float4 bj = g_topbox[jj];
        int cj = g_topcls[jj];
        float aj = (bj.z - bj.x) * (bj.w - bj.y);
        float ltx = fmaxf(bi.x, bj.x);
        float lty = fmaxf(bi.y, bj.y);
        float rbx = fminf(bi.z, bj.z);
        float rby = fminf(bi.w, bj.w);
        float w = fmaxf(rbx - ltx, 0.0f);
        float h = fmaxf(rby - lty, 0.0f);
        float inter = w * h;
        float den = ((ai + aj) - inter) + 1e-6f;
        // iou <= 0.5  <=>  inter <= 0.5*den   (den > 0 always)
        bool bit = valid && (cj == ci) && (inter <= 0.5f * den);
        unsigned word = __ballot_sync(0xFFFFFFFFu, bit);
        if (lane == 0) g_M[i * 32 + k] = word;
    }
}

// ---------------- single-block sequential suppression ----------------
// smem: M rows (32000 u32) + class masks (80*32 u32) + cls (1000 int)
#define SUPPRESS_SMEM ((32000 + 80 * 32 + 1000) * 4)

__global__ void suppress_kernel(float* __restrict__ out) {
    extern __shared__ unsigned smem[];
    unsigned* sM       = smem;                 // 32000
    unsigned* sClsMask = sM + 32000;           // 2560
    int*      sCls     = (int*)(sClsMask + 2560); // 1000

    int t = threadIdx.x;
    for (int i = t; i < 32000; i += 1024) sM[i] = g_M[i];
    for (int i = t; i < 2560;  i += 1024) sClsMask[i] = 0;
    if (t < TOPK) sCls[t] = g_topcls[t];
    __syncthreads();
    if (t < TOPK) atomicOr(&sClsMask[sCls[t] * 32 + (t >> 5)], 1u << (t & 31));
    __syncthreads();

    if (t < 32) {
        int lane = t;
        unsigned keep_w = (lane < 31) ? 0xFFFFFFFFu : 0x000000FFu;

        // depth-2 software prefetch of (set-row, class-row)
        unsigned set0 = sM[0 * 32 + lane];
        unsigned cls0 = sClsMask[sCls[0] * 32 + lane];
        unsigned set1 = sM[1 * 32 + lane];
        unsigned cls1 = sClsMask[sCls[1] * 32 + lane];

        for (int i = 0; i < TOPK; ++i) {
            unsigned setrow = set0, clsrow = cls0;
            set0 = set1; cls0 = cls1;
            int nx = i + 2;
            if (nx < TOPK) {
                set1 = sM[nx * 32 + lane];
                cls1 = sClsMask[sCls[nx] * 32 + lane];
            }
            unsigned kw = __shfl_sync(0xFFFFFFFFu, keep_w, i >> 5);
            unsigned apply = 0u - ((kw >> (i & 31)) & 1u);
            keep_w = (keep_w & ~(clsrow & apply)) | (setrow & apply);
        }

        #pragma unroll
        for (int b = 0; b < 32; ++b) {
            int j = lane * 32 + b;
            if (j < TOPK) out[3 * TOPK + j] = ((keep_w >> b) & 1u) ? 1.0f : 0.0f;
        }
    }
}

// ---------------- launch ----------------
extern "C" void kernel_launch(void* const* d_in, const int* in_sizes, int n_in,
                              void* d_out, int out_size) {
    const float* boxes  = (const float*)d_in[0];
    const float* scores = (const float*)d_in[1];
    float* out = (float*)d_out;
    int N = in_sizes[0] / 4;
    if (N > MAXN) N = MAXN;

    static bool attr_set = false;
    if (!attr_set) {
        cudaFuncSetAttribute(suppress_kernel,
                             cudaFuncAttributeMaxDynamicSharedMemorySize, SUPPRESS_SMEM);
        attr_set = true;
    }

    z_kernel<<<1, 256>>>();
    reduce_kernel<<<(N + 255) / 256, 256>>>(scores, N);
    scan_kernel<<<1, 256>>>(1);
    hist2_kernel<<<512, 256>>>(N);
    scan_kernel<<<1, 256>>>(2);
    hist3_kernel<<<512, 256>>>(N);
    scan_kernel<<<1, 256>>>(3);
    compact_kernel<<<512, 256>>>(N);
    sort_kernel<<<1, 1024>>>(boxes, out);
    mask_kernel<<<125, 256>>>();
    suppress_kernel<<<1, 1024, SUPPRESS_SMEM>>>(out);
}